// round 6
// baseline (speedup 1.0000x reference)
#include <cuda_runtime.h>
#include <cuda_bf16.h>
#include <cstdint>

#define N_NODES 100000
#define N_EDGES 1000000
#define HID 64
#define N_TILES 782                    // ceil(100000/128)
#define NODE_T (N_NODES * 16)          // k1-part thread domain
#define SCAN_BLOCKS 98

// ---- scratch (static device globals; no runtime allocation) ----
__device__ __align__(16) float g_xw_user[N_NODES * HID];
__device__ __align__(16) float g_xw_movie[N_NODES * HID];
__device__ float  g_deg[N_NODES];      // invariant: zero at call entry/exit
__device__ float  g_dinv[N_NODES];
__device__ int    g_count[N_NODES];    // invariant: zero at call entry/exit
__device__ int    g_off[N_NODES + 1];
__device__ int    g_cursor[N_NODES];
__device__ int    g_flag[SCAN_BLOCKS]; // scan lookback: blocksum+1; reset by k12
__device__ __align__(8) float2 g_edge[N_EDGES];   // {row_as_int_bits, norm}

// W1^T bf16 split image, row-major [n=128][k=128]
__device__ uint4 g_hB[2048];
__device__ uint4 g_lB[2048];

__device__ __forceinline__ unsigned pk2(__nv_bfloat16 a, __nv_bfloat16 b) {
    __nv_bfloat162 t; t.x = a; t.y = b;
    return *(unsigned*)&t;
}

// ---------------------------------------------------------------------------
// K12: fused node work (xw = x@W, W1 image, flag reset) + edge work
//      (weighted degree + in-degree count). Disjoint domains, no ordering dep.
// ---------------------------------------------------------------------------
__global__ __launch_bounds__(256) void k12(
    const float* __restrict__ ux, const float* __restrict__ mx,
    const float* __restrict__ Wu, const float* __restrict__ Wm,
    const float* __restrict__ W1,
    const int* __restrict__ ei, const float* __restrict__ ew) {
    int gid = blockIdx.x * blockDim.x + threadIdx.x;

    if (gid < NODE_T) {
        if (gid < SCAN_BLOCKS) g_flag[gid] = 0;
        if (gid < 16384) {          // W1 -> [n][k] bf16 hi/lo image
            int k = gid >> 7;
            int n = gid & 127;
            float w = W1[k * 128 + n];
            __nv_bfloat16 h = __float2bfloat16(w);
            __nv_bfloat16 l = __float2bfloat16(w - __bfloat162float(h));
            ((__nv_bfloat16*)g_hB)[n * 128 + k] = h;
            ((__nv_bfloat16*)g_lB)[n * 128 + k] = l;
        }
        int n = gid >> 4;
        int c = gid & 15;

        float4 su = make_float4(0.f, 0.f, 0.f, 0.f);
#pragma unroll
        for (int k = 0; k < 3; k++) {
            float xv = ux[n * 3 + k];
            float4 w = *(const float4*)(Wu + k * HID + c * 4);
            su.x += xv * w.x; su.y += xv * w.y; su.z += xv * w.z; su.w += xv * w.w;
        }
        *(float4*)(g_xw_user + (size_t)n * HID + c * 4) = su;

        float4 sm = make_float4(0.f, 0.f, 0.f, 0.f);
#pragma unroll
        for (int k = 0; k < 18; k++) {
            float xv = mx[n * 18 + k];
            float4 w = *(const float4*)(Wm + k * HID + c * 4);
            sm.x += xv * w.x; sm.y += xv * w.y; sm.z += xv * w.z; sm.w += xv * w.w;
        }
        *(float4*)(g_xw_movie + (size_t)n * HID + c * 4) = sm;
    } else {
        int e = gid - NODE_T;
        if (e < N_EDGES) {
            int col = ei[N_EDGES + e];
            atomicAdd(&g_deg[col], ew[e]);
            atomicAdd(&g_count[col], 1);
        }
    }
}

// ---------------------------------------------------------------------------
// SCAN: single launch. 98 resident blocks; publish blocksum+1 into g_flag,
//       each block sums predecessor aggregates (parallel poll). Also computes
//       dinv = rsqrt(deg+1) (self-loop) and RESETS deg/count for next call.
// ---------------------------------------------------------------------------
__global__ __launch_bounds__(256) void scan_k() {
    __shared__ int ts[256];
    __shared__ int sbase;
    int t = threadIdx.x;
    int b = blockIdx.x;
    int base = b * 1024 + t * 4;

    int v[4];
    int s = 0;
#pragma unroll
    for (int i = 0; i < 4; i++) {
        int idx = base + i;
        if (idx < N_NODES) {
            v[i] = g_count[idx];
            g_count[idx] = 0;
            g_dinv[idx] = rsqrtf(g_deg[idx] + 1.0f);
            g_deg[idx] = 0.f;
        } else v[i] = 0;
        s += v[i];
    }
    ts[t] = s;
    if (t == 0) sbase = 0;
    __syncthreads();
    for (int off = 1; off < 256; off <<= 1) {
        int add = (t >= off) ? ts[t - off] : 0;
        __syncthreads();
        ts[t] += add;
        __syncthreads();
    }
    if (t == 0) atomicExch(&g_flag[b], ts[255] + 1);   // publish (single word)
    if (t < b) {                                       // poll predecessors
        int w;
        do { w = atomicAdd(&g_flag[t], 0); } while (w == 0);
        atomicAdd(&sbase, w - 1);
    }
    __syncthreads();

    int run = sbase + ts[t] - s;   // global exclusive prefix for this thread
#pragma unroll
    for (int i = 0; i < 4; i++) {
        int idx = base + i;
        if (idx < N_NODES) {
            g_off[idx] = run;
            g_cursor[idx] = run;
        }
        run += v[i];
    }
    if (b == 0 && t == 0) g_off[N_NODES] = N_EDGES;
}

// ---------------------------------------------------------------------------
// F: fill CSR slots with (row, norm).
// ---------------------------------------------------------------------------
__global__ __launch_bounds__(256) void f_fill(
    const int* __restrict__ ei, const float* __restrict__ ew) {
    int e = blockIdx.x * blockDim.x + threadIdx.x;
    if (e >= N_EDGES) return;
    int row = ei[e];
    int col = ei[N_EDGES + e];
    float norm = g_dinv[row] * ew[e] * g_dinv[col];
    int pos = atomicAdd(&g_cursor[col], 1);
    g_edge[pos] = make_float2(__int_as_float(row), norm);
}

// ---------------------------------------------------------------------------
// GMMA: fused gather + split-bf16 mma.sync GEMM + relu/W2 epilogue.
//   512 threads. Phase 1: 16 warps gather 8 nodes each (warp-per-node,
//   unroll-4 edge pipelining), write split-bf16 rows to SMEM A images.
//   Phase 2: warps 0-7 run the m16n8k16 GEMM (3 chains) + epilogue.
// ---------------------------------------------------------------------------
#define PITCH    272
#define SM_AHI   0
#define SM_ALO   (128 * PITCH)
#define SM_BHI   (2 * 128 * PITCH)
#define SM_BLO   (3 * 128 * PITCH)
#define SM_B1    (4 * 128 * PITCH)
#define SM_W2    (SM_B1 + 512)
#define SM_TOT   (SM_W2 + 512)

__global__ __launch_bounds__(512, 1)
void gmma(const float* __restrict__ bu, const float* __restrict__ bm,
          const float* __restrict__ b1, const float* __restrict__ W2,
          const float* __restrict__ b2, float* __restrict__ out) {
    extern __shared__ char smem[];
    int tid = threadIdx.x;
    int wid = tid >> 5;
    int lane = tid & 31;
    int tile = blockIdx.x;

    // ---- stage shared weights ----
    if (tid < 128) {
        ((float*)(smem + SM_B1))[tid] = b1[tid];
        ((float*)(smem + SM_W2))[tid] = W2[tid];
    }
#pragma unroll
    for (int i = tid; i < 2048; i += 512) {
        int r = i >> 4, c16 = (i & 15) * 16;
        *(uint4*)(smem + SM_BHI + r * PITCH + c16) = g_hB[i];
        *(uint4*)(smem + SM_BLO + r * PITCH + c16) = g_lB[i];
    }

    // ---- phase 1: gather into SMEM A images ----
    {
        const float* src = (lane < 16) ? g_xw_user : g_xw_movie;
        const float* bias = (lane < 16) ? bu : bm;
        int c4 = (lane & 15) * 4;
        int k0b = ((lane < 16) ? c4 : (64 + c4)) * 2;   // byte offset in row

        for (int nl = wid; nl < 128; nl += 16) {
            int n = tile * 128 + nl;
            float4 a;
            if (n < N_NODES) {
                float din = g_dinv[n];
                float s = din * din;
                float4 v = *(const float4*)(src + n * HID + c4);
                a = make_float4(s * v.x, s * v.y, s * v.z, s * v.w);
                float4 bb = *(const float4*)(bias + c4);
                a.x += bb.x; a.y += bb.y; a.z += bb.z; a.w += bb.w;

                int j = g_off[n];
                int end = g_off[n + 1];
                for (; j + 4 <= end; j += 4) {
                    float2 e0 = g_edge[j],     e1 = g_edge[j + 1];
                    float2 e2 = g_edge[j + 2], e3 = g_edge[j + 3];
                    float4 u0 = *(const float4*)(src + __float_as_int(e0.x) * HID + c4);
                    float4 u1 = *(const float4*)(src + __float_as_int(e1.x) * HID + c4);
                    float4 u2 = *(const float4*)(src + __float_as_int(e2.x) * HID + c4);
                    float4 u3 = *(const float4*)(src + __float_as_int(e3.x) * HID + c4);
                    a.x += e0.y * u0.x + e1.y * u1.x + e2.y * u2.x + e3.y * u3.x;
                    a.y += e0.y * u0.y + e1.y * u1.y + e2.y * u2.y + e3.y * u3.y;
                    a.z += e0.y * u0.z + e1.y * u1.z + e2.y * u2.z + e3.y * u3.z;
                    a.w += e0.y * u0.w + e1.y * u1.w + e2.y * u2.w + e3.y * u3.w;
                }
                for (; j < end; j++) {
                    float2 ed = g_edge[j];
                    float4 u = *(const float4*)(src + __float_as_int(ed.x) * HID + c4);
                    a.x += ed.y * u.x; a.y += ed.y * u.y;
                    a.z += ed.y * u.z; a.w += ed.y * u.w;
                }
            } else {
                a = make_float4(0.f, 0.f, 0.f, 0.f);
            }

            __nv_bfloat16 h0 = __float2bfloat16(a.x), h1 = __float2bfloat16(a.y);
            __nv_bfloat16 h2 = __float2bfloat16(a.z), h3 = __float2bfloat16(a.w);
            __nv_bfloat16 l0 = __float2bfloat16(a.x - __bfloat162float(h0));
            __nv_bfloat16 l1 = __float2bfloat16(a.y - __bfloat162float(h1));
            __nv_bfloat16 l2 = __float2bfloat16(a.z - __bfloat162float(h2));
            __nv_bfloat16 l3 = __float2bfloat16(a.w - __bfloat162float(h3));
            char* rowp = smem + nl * PITCH + k0b;
            *(uint2*)(rowp + SM_AHI) = make_uint2(pk2(h0, h1), pk2(h2, h3));
            *(uint2*)(rowp + SM_ALO) = make_uint2(pk2(l0, l1), pk2(l2, l3));
        }
    }
    __syncthreads();

    // ---- phase 2: MMA (warps 0-7) ----
    if (wid < 8) {
        int w = wid;
        float acc[16][4];
#pragma unroll
        for (int nt = 0; nt < 16; nt++)
#pragma unroll
            for (int j = 0; j < 4; j++) acc[nt][j] = 0.f;

        int gq = lane >> 2;
        int q4 = (lane & 3) * 4;
        const int aoffs[3] = {SM_AHI, SM_AHI, SM_ALO};
        const int boffs[3] = {SM_BHI, SM_BLO, SM_BHI};

#pragma unroll
        for (int ch = 0; ch < 3; ch++) {
            const char* As = smem + aoffs[ch] + (w * 16 + gq) * PITCH;
            const char* Bs = smem + boffs[ch] + gq * PITCH;
#pragma unroll
            for (int ks = 0; ks < 8; ks++) {
                int kb = ks * 32 + q4;
                uint32_t a0 = *(const uint32_t*)(As + kb);
                uint32_t a1 = *(const uint32_t*)(As + 8 * PITCH + kb);
                uint32_t a2 = *(const uint32_t*)(As + kb + 16);
                uint32_t a3 = *(const uint32_t*)(As + 8 * PITCH + kb + 16);
#pragma unroll
                for (int nt = 0; nt < 16; nt++) {
                    uint32_t b0 = *(const uint32_t*)(Bs + nt * 8 * PITCH + kb);
                    uint32_t b1v = *(const uint32_t*)(Bs + nt * 8 * PITCH + kb + 16);
                    asm volatile(
                        "mma.sync.aligned.m16n8k16.row.col.f32.bf16.bf16.f32 "
                        "{%0,%1,%2,%3}, {%4,%5,%6,%7}, {%8,%9}, {%0,%1,%2,%3};"
                        : "+f"(acc[nt][0]), "+f"(acc[nt][1]),
                          "+f"(acc[nt][2]), "+f"(acc[nt][3])
                        : "r"(a0), "r"(a1), "r"(a2), "r"(a3), "r"(b0), "r"(b1v));
                }
            }
        }

        // epilogue: relu(acc + b1) . W2, lane-local then shfl over 4-lane groups
        const float* b1s = (const float*)(smem + SM_B1);
        const float* w2s = (const float*)(smem + SM_W2);
        float p0 = 0.f, p1 = 0.f;
#pragma unroll
        for (int nt = 0; nt < 16; nt++) {
            int cn = nt * 8 + (lane & 3) * 2;
            float bb0 = b1s[cn], bb1 = b1s[cn + 1];
            float ww0 = w2s[cn], ww1 = w2s[cn + 1];
            float t;
            t = acc[nt][0] + bb0; t = t > 0.f ? t : 0.f; p0 += t * ww0;
            t = acc[nt][1] + bb1; t = t > 0.f ? t : 0.f; p0 += t * ww1;
            t = acc[nt][2] + bb0; t = t > 0.f ? t : 0.f; p1 += t * ww0;
            t = acc[nt][3] + bb1; t = t > 0.f ? t : 0.f; p1 += t * ww1;
        }
        p0 += __shfl_xor_sync(0xFFFFFFFF, p0, 1);
        p0 += __shfl_xor_sync(0xFFFFFFFF, p0, 2);
        p1 += __shfl_xor_sync(0xFFFFFFFF, p1, 1);
        p1 += __shfl_xor_sync(0xFFFFFFFF, p1, 2);

        if ((lane & 3) == 0) {
            float bias2 = b2[0];
            int r0 = tile * 128 + w * 16 + gq;
            int r1 = r0 + 8;
            if (r0 < N_NODES) out[r0] = p0 + bias2;
            if (r1 < N_NODES) out[r1] = p1 + bias2;
        }
    }
}

// ---------------------------------------------------------------------------
extern "C" void kernel_launch(void* const* d_in, const int* in_sizes, int n_in,
                              void* d_out, int out_size) {
    const float* user_x   = (const float*)d_in[0];
    const float* movie_x  = (const float*)d_in[1];
    const int*   edge_idx = (const int*)d_in[2];    // int32 (JAX x64 disabled)
    const float* edge_w   = (const float*)d_in[3];
    const float* W_user   = (const float*)d_in[4];
    const float* b_user   = (const float*)d_in[5];
    const float* W_movie  = (const float*)d_in[6];
    const float* b_movie  = (const float*)d_in[7];
    const float* W1       = (const float*)d_in[8];
    const float* b1       = (const float*)d_in[9];
    const float* W2       = (const float*)d_in[10];
    const float* b2       = (const float*)d_in[11];
    float* out = (float*)d_out;

    static int smem_set = 0;
    if (!smem_set) {
        cudaFuncSetAttribute(gmma, cudaFuncAttributeMaxDynamicSharedMemorySize, SM_TOT);
        smem_set = 1;
    }

    k12    <<<(NODE_T + N_EDGES + 255) / 256, 256>>>(user_x, movie_x, W_user,
                                                     W_movie, W1, edge_idx, edge_w);
    scan_k <<<SCAN_BLOCKS, 256>>>();
    f_fill <<<(N_EDGES + 255) / 256, 256>>>(edge_idx, edge_w);
    gmma   <<<N_TILES, 512, SM_TOT>>>(b_user, b_movie, b1, W2, b2, out);
}

// round 7
// speedup vs baseline: 1.4040x; 1.4040x over previous
#include <cuda_runtime.h>
#include <cuda_bf16.h>
#include <cstdint>

#define N_NODES 100000
#define N_EDGES 1000000
#define HID 64
#define N_TILES 782                    // ceil(100000/128)
#define NODE_T (N_NODES * 16)          // node-part thread domain in k12
#define SCAN_BLOCKS 98

// ---- scratch (static device globals; no runtime allocation) ----
__device__ __align__(16) float g_xw_user[N_NODES * HID];
__device__ __align__(16) float g_xw_movie[N_NODES * HID];
__device__ float  g_deg[N_NODES];      // invariant: zero at call entry/exit
__device__ float  g_dinv[N_NODES];
__device__ int    g_count[N_NODES];    // invariant: zero at call entry/exit
__device__ int    g_off[N_NODES + 1];
__device__ int    g_cursor[N_NODES];
__device__ int    g_flag[SCAN_BLOCKS]; // scan lookback: blocksum+1; reset by k12
__device__ __align__(8) float2 g_edge[N_EDGES];   // {row_as_int_bits, norm}

// bf16 split images, row-major:
//   g_hA/g_lA: [tile][m=128][k=128], g_hB/g_lB: [n=128][k=128] (W1^T)
__device__ uint4 g_hA[N_TILES * 2048];
__device__ uint4 g_lA[N_TILES * 2048];
__device__ uint4 g_hB[2048];
__device__ uint4 g_lB[2048];

__device__ __forceinline__ unsigned pk2(__nv_bfloat16 a, __nv_bfloat16 b) {
    __nv_bfloat162 t; t.x = a; t.y = b;
    return *(unsigned*)&t;
}

// ---------------------------------------------------------------------------
// K12: fused node work (xw = x@W, W1 image, flag reset) + edge work
//      (weighted degree + in-degree count). Disjoint domains.
// ---------------------------------------------------------------------------
__global__ __launch_bounds__(256) void k12(
    const float* __restrict__ ux, const float* __restrict__ mx,
    const float* __restrict__ Wu, const float* __restrict__ Wm,
    const float* __restrict__ W1,
    const int* __restrict__ ei, const float* __restrict__ ew) {
    int gid = blockIdx.x * blockDim.x + threadIdx.x;

    if (gid < NODE_T) {
        if (gid < SCAN_BLOCKS) g_flag[gid] = 0;
        if (gid < 16384) {          // W1 -> [n][k] bf16 hi/lo image
            int k = gid >> 7;
            int n = gid & 127;
            float w = W1[k * 128 + n];
            __nv_bfloat16 h = __float2bfloat16(w);
            __nv_bfloat16 l = __float2bfloat16(w - __bfloat162float(h));
            ((__nv_bfloat16*)g_hB)[n * 128 + k] = h;
            ((__nv_bfloat16*)g_lB)[n * 128 + k] = l;
        }
        int n = gid >> 4;
        int c = gid & 15;

        float4 su = make_float4(0.f, 0.f, 0.f, 0.f);
#pragma unroll
        for (int k = 0; k < 3; k++) {
            float xv = ux[n * 3 + k];
            float4 w = *(const float4*)(Wu + k * HID + c * 4);
            su.x += xv * w.x; su.y += xv * w.y; su.z += xv * w.z; su.w += xv * w.w;
        }
        *(float4*)(g_xw_user + (size_t)n * HID + c * 4) = su;

        float4 sm = make_float4(0.f, 0.f, 0.f, 0.f);
#pragma unroll
        for (int k = 0; k < 18; k++) {
            float xv = mx[n * 18 + k];
            float4 w = *(const float4*)(Wm + k * HID + c * 4);
            sm.x += xv * w.x; sm.y += xv * w.y; sm.z += xv * w.z; sm.w += xv * w.w;
        }
        *(float4*)(g_xw_movie + (size_t)n * HID + c * 4) = sm;
    } else {
        int e = gid - NODE_T;
        if (e < N_EDGES) {
            int col = ei[N_EDGES + e];
            atomicAdd(&g_deg[col], ew[e]);
            atomicAdd(&g_count[col], 1);
        }
    }
}

// ---------------------------------------------------------------------------
// SCAN: single launch, 98 resident blocks, publish-and-sum lookback.
//       Fuses dinv = rsqrt(deg+1) and resets deg/count for the next call.
// ---------------------------------------------------------------------------
__global__ __launch_bounds__(256) void scan_k() {
    __shared__ int ts[256];
    __shared__ int sbase;
    int t = threadIdx.x;
    int b = blockIdx.x;
    int base = b * 1024 + t * 4;

    int v[4];
    int s = 0;
#pragma unroll
    for (int i = 0; i < 4; i++) {
        int idx = base + i;
        if (idx < N_NODES) {
            v[i] = g_count[idx];
            g_count[idx] = 0;
            g_dinv[idx] = rsqrtf(g_deg[idx] + 1.0f);
            g_deg[idx] = 0.f;
        } else v[i] = 0;
        s += v[i];
    }
    ts[t] = s;
    if (t == 0) sbase = 0;
    __syncthreads();
    for (int off = 1; off < 256; off <<= 1) {
        int add = (t >= off) ? ts[t - off] : 0;
        __syncthreads();
        ts[t] += add;
        __syncthreads();
    }
    if (t == 0) atomicExch(&g_flag[b], ts[255] + 1);   // publish
    if (t < b) {                                       // poll predecessors
        int w;
        do { w = atomicAdd(&g_flag[t], 0); } while (w == 0);
        atomicAdd(&sbase, w - 1);
    }
    __syncthreads();

    int run = sbase + ts[t] - s;
#pragma unroll
    for (int i = 0; i < 4; i++) {
        int idx = base + i;
        if (idx < N_NODES) {
            g_off[idx] = run;
            g_cursor[idx] = run;
        }
        run += v[i];
    }
    if (b == 0 && t == 0) g_off[N_NODES] = N_EDGES;
}

// ---------------------------------------------------------------------------
// F: fill CSR slots with (row, norm).
// ---------------------------------------------------------------------------
__global__ __launch_bounds__(256) void f_fill(
    const int* __restrict__ ei, const float* __restrict__ ew) {
    int e = blockIdx.x * blockDim.x + threadIdx.x;
    if (e >= N_EDGES) return;
    int row = ei[e];
    int col = ei[N_EDGES + e];
    float norm = g_dinv[row] * ew[e] * g_dinv[col];
    int pos = atomicAdd(&g_cursor[col], 1);
    g_edge[pos] = make_float2(__int_as_float(row), norm);
}

// ---------------------------------------------------------------------------
// G: gather (HIGH OCCUPANCY — this kernel is L2-latency bound and needs
//    warps; R6 proved fusing it into an occ-1 kernel costs 2-3x).
//    Warp per destination node; unroll-4 edge pipelining; bias fused;
//    split-bf16 hi/lo written to row-major tile images.
// ---------------------------------------------------------------------------
__global__ __launch_bounds__(256) void g_gather(
    const float* __restrict__ bu, const float* __restrict__ bm) {
    unsigned gid = blockIdx.x * blockDim.x + threadIdx.x;
    unsigned n = gid >> 5;
    int c = gid & 31;
    if (n >= N_NODES) return;

    const float* src = (c < 16) ? g_xw_user : g_xw_movie;
    const float* bias = (c < 16) ? bu : bm;
    int c4 = (c & 15) * 4;

    float din = g_dinv[n];
    float s = din * din;
    float4 v = *(const float4*)(src + (size_t)n * HID + c4);
    float4 a = make_float4(s * v.x, s * v.y, s * v.z, s * v.w);
    float4 bb = *(const float4*)(bias + c4);
    a.x += bb.x; a.y += bb.y; a.z += bb.z; a.w += bb.w;

    int j = g_off[n];
    int end = g_off[n + 1];
    for (; j + 4 <= end; j += 4) {
        float2 e0 = g_edge[j],     e1 = g_edge[j + 1];
        float2 e2 = g_edge[j + 2], e3 = g_edge[j + 3];
        float4 u0 = *(const float4*)(src + __float_as_int(e0.x) * HID + c4);
        float4 u1 = *(const float4*)(src + __float_as_int(e1.x) * HID + c4);
        float4 u2 = *(const float4*)(src + __float_as_int(e2.x) * HID + c4);
        float4 u3 = *(const float4*)(src + __float_as_int(e3.x) * HID + c4);
        a.x += e0.y * u0.x + e1.y * u1.x + e2.y * u2.x + e3.y * u3.x;
        a.y += e0.y * u0.y + e1.y * u1.y + e2.y * u2.y + e3.y * u3.y;
        a.z += e0.y * u0.z + e1.y * u1.z + e2.y * u2.z + e3.y * u3.z;
        a.w += e0.y * u0.w + e1.y * u1.w + e2.y * u2.w + e3.y * u3.w;
    }
    for (; j < end; j++) {
        float2 ed = g_edge[j];
        float4 u = *(const float4*)(src + __float_as_int(ed.x) * HID + c4);
        a.x += ed.y * u.x; a.y += ed.y * u.y;
        a.z += ed.y * u.z; a.w += ed.y * u.w;
    }

    __nv_bfloat16 h0 = __float2bfloat16(a.x), h1 = __float2bfloat16(a.y);
    __nv_bfloat16 h2 = __float2bfloat16(a.z), h3 = __float2bfloat16(a.w);
    __nv_bfloat16 l0 = __float2bfloat16(a.x - __bfloat162float(h0));
    __nv_bfloat16 l1 = __float2bfloat16(a.y - __bfloat162float(h1));
    __nv_bfloat16 l2 = __float2bfloat16(a.z - __bfloat162float(h2));
    __nv_bfloat16 l3 = __float2bfloat16(a.w - __bfloat162float(h3));

    unsigned tile = n >> 7;
    unsigned m = n & 127;
    int k0 = (c < 16) ? c4 : (64 + c4);
    size_t off = (size_t)tile * 32768 + m * 256 + k0 * 2;   // bytes
    *(uint2*)((char*)g_hA + off) = make_uint2(pk2(h0, h1), pk2(h2, h3));
    *(uint2*)((char*)g_lA + off) = make_uint2(pk2(l0, l1), pk2(l2, l3));
}

// ---------------------------------------------------------------------------
// K5: split-bf16 GEMM via mma.sync.m16n8k16 + fused relu/W2 epilogue.
//     256 thr (8 warps); warp w owns rows 16w..16w+15, all 128 cols.
// ---------------------------------------------------------------------------
#define PITCH    272
#define SM_AHI   0
#define SM_ALO   (128 * PITCH)
#define SM_BHI   (2 * 128 * PITCH)
#define SM_BLO   (3 * 128 * PITCH)
#define SM_B1    (4 * 128 * PITCH)
#define SM_W2    (SM_B1 + 512)
#define SM_TOT   (SM_W2 + 512)

__global__ __launch_bounds__(256, 1)
void k5_mma(const float* __restrict__ b1, const float* __restrict__ W2,
            const float* __restrict__ b2, float* __restrict__ out) {
    extern __shared__ char smem[];
    int tid = threadIdx.x;
    int w = tid >> 5;
    int lane = tid & 31;
    int tile = blockIdx.x;

    if (tid < 128) {
        ((float*)(smem + SM_B1))[tid] = b1[tid];
        ((float*)(smem + SM_W2))[tid] = W2[tid];
    }
    {
        const uint4* gah = g_hA + (size_t)tile * 2048;
        const uint4* gal = g_lA + (size_t)tile * 2048;
#pragma unroll
        for (int i = tid; i < 2048; i += 256) {
            int r = i >> 4, c16 = (i & 15) * 16;
            *(uint4*)(smem + SM_AHI + r * PITCH + c16) = gah[i];
            *(uint4*)(smem + SM_ALO + r * PITCH + c16) = gal[i];
            *(uint4*)(smem + SM_BHI + r * PITCH + c16) = g_hB[i];
            *(uint4*)(smem + SM_BLO + r * PITCH + c16) = g_lB[i];
        }
    }
    __syncthreads();

    float acc[16][4];
#pragma unroll
    for (int nt = 0; nt < 16; nt++)
#pragma unroll
        for (int j = 0; j < 4; j++) acc[nt][j] = 0.f;

    int gq = lane >> 2;
    int q4 = (lane & 3) * 4;
    const int aoffs[3] = {SM_AHI, SM_AHI, SM_ALO};
    const int boffs[3] = {SM_BHI, SM_BLO, SM_BHI};

#pragma unroll
    for (int ch = 0; ch < 3; ch++) {
        const char* As = smem + aoffs[ch] + (w * 16 + gq) * PITCH;
        const char* Bs = smem + boffs[ch] + gq * PITCH;
#pragma unroll
        for (int ks = 0; ks < 8; ks++) {
            int kb = ks * 32 + q4;
            uint32_t a0 = *(const uint32_t*)(As + kb);
            uint32_t a1 = *(const uint32_t*)(As + 8 * PITCH + kb);
            uint32_t a2 = *(const uint32_t*)(As + kb + 16);
            uint32_t a3 = *(const uint32_t*)(As + 8 * PITCH + kb + 16);
#pragma unroll
            for (int nt = 0; nt < 16; nt++) {
                uint32_t b0 = *(const uint32_t*)(Bs + nt * 8 * PITCH + kb);
                uint32_t b1v = *(const uint32_t*)(Bs + nt * 8 * PITCH + kb + 16);
                asm volatile(
                    "mma.sync.aligned.m16n8k16.row.col.f32.bf16.bf16.f32 "
                    "{%0,%1,%2,%3}, {%4,%5,%6,%7}, {%8,%9}, {%0,%1,%2,%3};"
                    : "+f"(acc[nt][0]), "+f"(acc[nt][1]),
                      "+f"(acc[nt][2]), "+f"(acc[nt][3])
                    : "r"(a0), "r"(a1), "r"(a2), "r"(a3), "r"(b0), "r"(b1v));
            }
        }
    }

    const float* b1s = (const float*)(smem + SM_B1);
    const float* w2s = (const float*)(smem + SM_W2);
    float p0 = 0.f, p1 = 0.f;
#pragma unroll
    for (int nt = 0; nt < 16; nt++) {
        int cn = nt * 8 + (lane & 3) * 2;
        float bb0 = b1s[cn], bb1 = b1s[cn + 1];
        float ww0 = w2s[cn], ww1 = w2s[cn + 1];
        float t;
        t = acc[nt][0] + bb0; t = t > 0.f ? t : 0.f; p0 += t * ww0;
        t = acc[nt][1] + bb1; t = t > 0.f ? t : 0.f; p0 += t * ww1;
        t = acc[nt][2] + bb0; t = t > 0.f ? t : 0.f; p1 += t * ww0;
        t = acc[nt][3] + bb1; t = t > 0.f ? t : 0.f; p1 += t * ww1;
    }
    p0 += __shfl_xor_sync(0xFFFFFFFF, p0, 1);
    p0 += __shfl_xor_sync(0xFFFFFFFF, p0, 2);
    p1 += __shfl_xor_sync(0xFFFFFFFF, p1, 1);
    p1 += __shfl_xor_sync(0xFFFFFFFF, p1, 2);

    if ((lane & 3) == 0) {
        float bias2 = b2[0];
        int r0 = tile * 128 + w * 16 + gq;
        int r1 = r0 + 8;
        if (r0 < N_NODES) out[r0] = p0 + bias2;
        if (r1 < N_NODES) out[r1] = p1 + bias2;
    }
}

// ---------------------------------------------------------------------------
extern "C" void kernel_launch(void* const* d_in, const int* in_sizes, int n_in,
                              void* d_out, int out_size) {
    const float* user_x   = (const float*)d_in[0];
    const float* movie_x  = (const float*)d_in[1];
    const int*   edge_idx = (const int*)d_in[2];    // int32 (JAX x64 disabled)
    const float* edge_w   = (const float*)d_in[3];
    const float* W_user   = (const float*)d_in[4];
    const float* b_user   = (const float*)d_in[5];
    const float* W_movie  = (const float*)d_in[6];
    const float* b_movie  = (const float*)d_in[7];
    const float* W1       = (const float*)d_in[8];
    const float* b1       = (const float*)d_in[9];
    const float* W2       = (const float*)d_in[10];
    const float* b2       = (const float*)d_in[11];
    float* out = (float*)d_out;

    static int smem_set = 0;
    if (!smem_set) {
        cudaFuncSetAttribute(k5_mma, cudaFuncAttributeMaxDynamicSharedMemorySize, SM_TOT);
        smem_set = 1;
    }

    k12     <<<(NODE_T + N_EDGES + 255) / 256, 256>>>(user_x, movie_x, W_user,
                                                      W_movie, W1, edge_idx, edge_w);
    scan_k  <<<SCAN_BLOCKS, 256>>>();
    f_fill  <<<(N_EDGES + 255) / 256, 256>>>(edge_idx, edge_w);
    g_gather<<<(N_NODES * 32 + 255) / 256, 256>>>(b_user, b_movie);
    k5_mma  <<<N_TILES, 256, SM_TOT>>>(b1, W2, b2, out);
}

// round 9
// speedup vs baseline: 2.6833x; 1.9112x over previous
#include <cuda_runtime.h>
#include <cstdint>

#define N_NODES 100000
#define N_EDGES 1000000
#define N_TILES 782                    // ceil(100000/128)
#define FEAT_T (N_NODES * 24)          // feature-pack thread domain
#define SCAN_BLOCKS 98
#define TAIL_BASE (FEAT_T + N_EDGES)

// ---- scratch (static device globals; zero-initialized, no runtime alloc) ----
__device__ __align__(16) float g_feat[N_NODES * 24];        // [n][24]: 3 user + 18 movie + 3 zero
__device__ __align__(16) float g_agg[N_TILES * 128 * 24];   // aggregated raw features
__device__ float  g_Weff[24 * 128];    // [Wu@W1a ; Wm@W1b]; rows 21..23 stay zero
__device__ float  g_beff[128];         // bu@W1a + bm@W1b + b1
__device__ float  g_deg[N_NODES];      // invariant: zero at call entry/exit
__device__ float  g_dinv[N_NODES];
__device__ int    g_count[N_NODES];    // invariant: zero at call entry/exit
__device__ int    g_off[N_NODES + 1];
__device__ int    g_cursor[N_NODES];
__device__ int    g_flag[SCAN_BLOCKS]; // scan lookback; reset by k12
__device__ __align__(8) float2 g_edge[N_EDGES];   // {row_as_int_bits, norm}

// ---------------------------------------------------------------------------
// K12: fused — (a) pack raw features into g_feat[n][24] (pad zeros),
//      (b) edge-degree atomics, (c) tail: Weff / beff precompute + flag reset.
// ---------------------------------------------------------------------------
__global__ __launch_bounds__(256) void k12(
    const float* __restrict__ ux, const float* __restrict__ mx,
    const float* __restrict__ Wu, const float* __restrict__ Wm,
    const float* __restrict__ W1, const float* __restrict__ bu,
    const float* __restrict__ bm, const float* __restrict__ b1,
    const int* __restrict__ ei, const float* __restrict__ ew) {
    int gid = blockIdx.x * blockDim.x + threadIdx.x;

    if (gid < FEAT_T) {
        int n = gid / 24;
        int f = gid - n * 24;
        float v = 0.f;
        if (f < 3) v = ux[n * 3 + f];
        else if (f < 21) v = mx[n * 18 + f - 3];
        g_feat[n * 24 + f] = v;
    } else if (gid < TAIL_BASE) {
        int e = gid - FEAT_T;
        int col = ei[N_EDGES + e];
        atomicAdd(&g_deg[col], ew[e]);
        atomicAdd(&g_count[col], 1);
    } else {
        int t = gid - TAIL_BASE;
        if (t < 2688) {                       // Weff[k][j], k<21
            int k = t >> 7, j = t & 127;
            float s = 0.f;
            if (k < 3) {
#pragma unroll 8
                for (int c = 0; c < 64; c++)
                    s += Wu[k * 64 + c] * W1[c * 128 + j];
            } else {
#pragma unroll 8
                for (int c = 0; c < 64; c++)
                    s += Wm[(k - 3) * 64 + c] * W1[(64 + c) * 128 + j];
            }
            g_Weff[k * 128 + j] = s;
        } else if (t < 2816) {                // beff[j]
            int j = t - 2688;
            float s = b1[j];
#pragma unroll 8
            for (int c = 0; c < 64; c++) {
                s += bu[c] * W1[c * 128 + j];
                s += bm[c] * W1[(64 + c) * 128 + j];
            }
            g_beff[j] = s;
        } else if (t < 2816 + SCAN_BLOCKS) {
            g_flag[t - 2816] = 0;
        }
    }
}

// ---------------------------------------------------------------------------
// SCAN: single launch, 98 resident blocks, publish-and-sum lookback.
//       Fuses dinv = rsqrt(deg+1) and resets deg/count for the next call.
// ---------------------------------------------------------------------------
__global__ __launch_bounds__(256) void scan_k() {
    __shared__ int ts[256];
    __shared__ int sbase;
    int t = threadIdx.x;
    int b = blockIdx.x;
    int base = b * 1024 + t * 4;

    int v[4];
    int s = 0;
#pragma unroll
    for (int i = 0; i < 4; i++) {
        int idx = base + i;
        if (idx < N_NODES) {
            v[i] = g_count[idx];
            g_count[idx] = 0;
            g_dinv[idx] = rsqrtf(g_deg[idx] + 1.0f);
            g_deg[idx] = 0.f;
        } else v[i] = 0;
        s += v[i];
    }
    ts[t] = s;
    if (t == 0) sbase = 0;
    __syncthreads();
    for (int off = 1; off < 256; off <<= 1) {
        int add = (t >= off) ? ts[t - off] : 0;
        __syncthreads();
        ts[t] += add;
        __syncthreads();
    }
    if (t == 0) atomicExch(&g_flag[b], ts[255] + 1);   // publish
    if (t < b) {                                       // poll predecessors
        int w;
        do { w = atomicAdd(&g_flag[t], 0); } while (w == 0);
        atomicAdd(&sbase, w - 1);
    }
    __syncthreads();

    int run = sbase + ts[t] - s;
#pragma unroll
    for (int i = 0; i < 4; i++) {
        int idx = base + i;
        if (idx < N_NODES) {
            g_off[idx] = run;
            g_cursor[idx] = run;
        }
        run += v[i];
    }
    if (b == 0 && t == 0) g_off[N_NODES] = N_EDGES;
}

// ---------------------------------------------------------------------------
// F: fill CSR slots with (row, norm).
// ---------------------------------------------------------------------------
__global__ __launch_bounds__(256) void f_fill(
    const int* __restrict__ ei, const float* __restrict__ ew) {
    int e = blockIdx.x * blockDim.x + threadIdx.x;
    if (e >= N_EDGES) return;
    int row = ei[e];
    int col = ei[N_EDGES + e];
    float norm = g_dinv[row] * ew[e] * g_dinv[col];
    int pos = atomicAdd(&g_cursor[col], 1);
    g_edge[pos] = make_float2(__int_as_float(row), norm);
}

// ---------------------------------------------------------------------------
// G2: gather RAW features (96B/edge, 5.3x less than before). 8 threads per
//     node, lanes 0-5 each own one float4 chunk of the 24-float feature row.
//     High occupancy, no smem — L2-latency tolerant.
// ---------------------------------------------------------------------------
__global__ __launch_bounds__(256) void g_gather2() {
    unsigned gid = blockIdx.x * blockDim.x + threadIdx.x;
    unsigned n = gid >> 3;
    int l8 = gid & 7;
    if (n >= N_NODES || l8 >= 6) return;

    const float4* f4 = (const float4*)g_feat;
    float din = g_dinv[n];
    float s = din * din;                       // self-loop norm
    float4 v = f4[n * 6 + l8];
    float4 a = make_float4(s * v.x, s * v.y, s * v.z, s * v.w);

    int j = g_off[n];
    int end = g_off[n + 1];
    for (; j + 4 <= end; j += 4) {
        float2 e0 = g_edge[j],     e1 = g_edge[j + 1];
        float2 e2 = g_edge[j + 2], e3 = g_edge[j + 3];
        float4 u0 = f4[__float_as_int(e0.x) * 6 + l8];
        float4 u1 = f4[__float_as_int(e1.x) * 6 + l8];
        float4 u2 = f4[__float_as_int(e2.x) * 6 + l8];
        float4 u3 = f4[__float_as_int(e3.x) * 6 + l8];
        a.x += e0.y * u0.x + e1.y * u1.x + e2.y * u2.x + e3.y * u3.x;
        a.y += e0.y * u0.y + e1.y * u1.y + e2.y * u2.y + e3.y * u3.y;
        a.z += e0.y * u0.z + e1.y * u1.z + e2.y * u2.z + e3.y * u3.z;
        a.w += e0.y * u0.w + e1.y * u1.w + e2.y * u2.w + e3.y * u3.w;
    }
    for (; j < end; j++) {
        float2 ed = g_edge[j];
        float4 u = f4[__float_as_int(ed.x) * 6 + l8];
        a.x += ed.y * u.x; a.y += ed.y * u.y;
        a.z += ed.y * u.z; a.w += ed.y * u.w;
    }
    *(float4*)&g_agg[n * 24 + l8 * 4] = a;
}

// ---------------------------------------------------------------------------
// MLP: act[n] = agg[n] @ Weff + beff (N x 24 @ 24 x 128, fp32 tiled GEMM,
//      8x8 register blocking), out[n] = relu(act).W2 + b2.
//      Static smem 35KB, 256 threads, 128 nodes/block.
// ---------------------------------------------------------------------------
__global__ __launch_bounds__(256) void mlp(
    const float* __restrict__ W2, const float* __restrict__ b2,
    float* __restrict__ out) {
    __shared__ float s_agg[128 * 28];      // pitch 28 (16B-aligned float4 slots)
    __shared__ float s_weff[24 * 128];
    __shared__ float s_red[128 * 16];
    __shared__ float s_beff[128];
    __shared__ float s_w2[128];

    int tid = threadIdx.x;
    int blk = blockIdx.x;

    // stage agg (768 float4) and Weff (768 float4)
    {
        const float4* ga4 = (const float4*)g_agg + blk * 768;
        const float4* gw4 = (const float4*)g_Weff;
#pragma unroll
        for (int i = tid; i < 768; i += 256) {
            int r = i / 6, c = i - r * 6;
            *(float4*)&s_agg[r * 28 + c * 4] = ga4[i];
            ((float4*)s_weff)[i] = gw4[i];
        }
    }
    if (tid < 128) {
        s_beff[tid] = g_beff[tid];
        s_w2[tid] = W2[tid];
    }
    __syncthreads();

    int cg = tid & 15;    // col group: cols cg*8..cg*8+7
    int ng = tid >> 4;    // node group: nodes ng*8..ng*8+7

    float acc[8][8];
#pragma unroll
    for (int i = 0; i < 8; i++)
#pragma unroll
        for (int j = 0; j < 8; j++) acc[i][j] = 0.f;

#pragma unroll
    for (int kk = 0; kk < 24; kk++) {
        float4 wa = *(const float4*)&s_weff[kk * 128 + cg * 8];
        float4 wb = *(const float4*)&s_weff[kk * 128 + cg * 8 + 4];
        float hv[8];
#pragma unroll
        for (int i = 0; i < 8; i++)
            hv[i] = s_agg[(ng * 8 + i) * 28 + kk];
#pragma unroll
        for (int i = 0; i < 8; i++) {
            acc[i][0] += hv[i] * wa.x;
            acc[i][1] += hv[i] * wa.y;
            acc[i][2] += hv[i] * wa.z;
            acc[i][3] += hv[i] * wa.w;
            acc[i][4] += hv[i] * wb.x;
            acc[i][5] += hv[i] * wb.y;
            acc[i][6] += hv[i] * wb.z;
            acc[i][7] += hv[i] * wb.w;
        }
    }

    // epilogue: relu(acc + beff) . W2
    float bev[8], w2v[8];
#pragma unroll
    for (int j = 0; j < 8; j++) {
        bev[j] = s_beff[cg * 8 + j];
        w2v[j] = s_w2[cg * 8 + j];
    }
#pragma unroll
    for (int i = 0; i < 8; i++) {
        float p = 0.f;
#pragma unroll
        for (int j = 0; j < 8; j++) {
            float t = acc[i][j] + bev[j];
            t = t > 0.f ? t : 0.f;
            p += t * w2v[j];
        }
        s_red[(ng * 8 + i) * 16 + cg] = p;
    }
    __syncthreads();
    if (tid < 128) {
        int n = blk * 128 + tid;
        if (n < N_NODES) {
            float s = 0.f;
#pragma unroll
            for (int g = 0; g < 16; g++) s += s_red[tid * 16 + g];
            out[n] = s + b2[0];
        }
    }
}

// ---------------------------------------------------------------------------
extern "C" void kernel_launch(void* const* d_in, const int* in_sizes, int n_in,
                              void* d_out, int out_size) {
    const float* user_x   = (const float*)d_in[0];
    const float* movie_x  = (const float*)d_in[1];
    const int*   edge_idx = (const int*)d_in[2];    // int32 (JAX x64 disabled)
    const float* edge_w   = (const float*)d_in[3];
    const float* W_user   = (const float*)d_in[4];
    const float* b_user   = (const float*)d_in[5];
    const float* W_movie  = (const float*)d_in[6];
    const float* b_movie  = (const float*)d_in[7];
    const float* W1       = (const float*)d_in[8];
    const float* b1       = (const float*)d_in[9];
    const float* W2       = (const float*)d_in[10];
    const float* b2       = (const float*)d_in[11];
    float* out = (float*)d_out;

    k12      <<<(TAIL_BASE + 4096 + 255) / 256, 256>>>(
        user_x, movie_x, W_user, W_movie, W1, b_user, b_movie, b1,
        edge_idx, edge_w);
    scan_k   <<<SCAN_BLOCKS, 256>>>();
    f_fill   <<<(N_EDGES + 255) / 256, 256>>>(edge_idx, edge_w);
    g_gather2<<<(N_NODES * 8 + 255) / 256, 256>>>();
    mlp      <<<N_TILES, 256>>>(W2, b2, out);
}